// round 1
// baseline (speedup 1.0000x reference)
#include <cuda_runtime.h>
#include <math.h>

#define HW      131072      // 256*512
#define W_IMG   512
#define H_IMG   256
#define NC      256
#define NB      2
#define NOUT    16          // 13 pos + 1 reg + 2 off

// Scratch for evident = relu(pos conv): [2,13,H,W]
__device__ float g_ev[NB * 13 * HW];

// ---------------- compile-time Hough tables ----------------
// score(y,x) = sum_{oy,ox in [-16,16]} w[region(-oy,-ox)] * e_{region(-oy,-ox)}(y+oy, x+ox)
// With tile index iy = oy+16, ix = ox+16: channel = region(16-iy, 16-ix),
// tap offset into a 64-wide shared tile = iy*64 + ix.
// Angle bin done with exact integer sign logic (matches numpy degrees(arctan2)
// which lands exactly on 0/90/180/270 for axis pixels).
struct HTab {
    alignas(16) unsigned short off[1184]; // per-region lists, each padded to mult of 8
    int   start[14];
    float w[13];
};

constexpr int region_of(int ys, int xs) {
    int r2 = ys * ys + xs * xs;
    if (r2 <= 4) return 0;
    int ring = (r2 <= 64) ? 0 : (r2 <= 256) ? 1 : 2;
    int bin = 0;
    if (ys > 0)      bin = (xs > 0) ? 0 : 1;
    else if (ys < 0) bin = (xs < 0) ? 2 : 3;
    else             bin = (xs > 0) ? 0 : 2;   // ys==0 row (origin is r2<=4)
    return 1 + ring * 4 + bin;
}

constexpr HTab make_tab() {
    HTab t{};
    int cnt[13] = {};
    for (int iy = 0; iy < 33; iy++)
        for (int ix = 0; ix < 33; ix++)
            cnt[region_of(16 - iy, 16 - ix)]++;
    int pos = 0;
    for (int r = 0; r < 13; r++) {
        t.start[r] = pos;
        t.w[r] = 1.0f / (float)cnt[r];
        pos += (cnt[r] + 7) & ~7;
    }
    t.start[13] = pos;
    int cur[13] = {};
    for (int r = 0; r < 13; r++) cur[r] = t.start[r];
    for (int iy = 0; iy < 33; iy++)
        for (int ix = 0; ix < 33; ix++) {
            int r = region_of(16 - iy, 16 - ix);
            t.off[cur[r]++] = (unsigned short)(iy * 64 + ix);
        }
    // pad with offsets pointing into the zeroed shared slab (index 4096..6143)
    for (int r = 0; r < 13; r++)
        while (cur[r] < t.start[r + 1]) t.off[cur[r]++] = 4096;
    return t;
}

__constant__ HTab g_tab = make_tab();

// ---------------- Kernel A: fused 1x1 convs (16 out channels) ----------------
// 8 pixels/thread, f32x2 packed FMA, weights in shared as duplicated {w,w} pairs.
#define FMA2(d, a, b) asm("fma.rn.f32x2 %0, %1, %2, %0;" : "+l"(d) : "l"(a), "l"(b))

__global__ void __launch_bounds__(128) k_head(
    const float* __restrict__ x,
    const float* __restrict__ pos_w, const float* __restrict__ pos_b,
    const float* __restrict__ reg_w, const float* __restrict__ reg_b,
    const float* __restrict__ off_w, const float* __restrict__ off_b,
    float* __restrict__ out)
{
    __shared__ __align__(16) unsigned long long wdup[NC * NOUT];

    const int tid = threadIdx.x;
    for (int i = tid; i < NC * NOUT; i += 128) {
        int c = i >> 4, o = i & 15;
        float w = (o < 13) ? pos_w[o * NC + c]
                : (o == 13) ? reg_w[c]
                : off_w[(o - 14) * NC + c];
        unsigned int u = __float_as_uint(w);
        wdup[i] = (unsigned long long)u | ((unsigned long long)u << 32);
    }
    __syncthreads();

    const int b  = blockIdx.y;
    const int pA = blockIdx.x * 1024 + tid * 4;   // 512 px group A
    const int pB = pA + 512;                       // 512 px group B
    const float* xb = x + (size_t)b * NC * HW;

    unsigned long long acc[4][NOUT];
    #pragma unroll
    for (int g = 0; g < 4; g++)
        #pragma unroll
        for (int o = 0; o < NOUT; o++) acc[g][o] = 0ull;

    #pragma unroll 2
    for (int c = 0; c < NC; c++) {
        ulonglong2 xa = *reinterpret_cast<const ulonglong2*>(xb + (size_t)c * HW + pA);
        ulonglong2 xc = *reinterpret_cast<const ulonglong2*>(xb + (size_t)c * HW + pB);
        const ulonglong2* wp = reinterpret_cast<const ulonglong2*>(wdup + c * NOUT);
        #pragma unroll
        for (int k = 0; k < 8; k++) {
            ulonglong2 wv = wp[k];   // {w(2k),w(2k)} , {w(2k+1),w(2k+1)}
            FMA2(acc[0][2 * k],     xa.x, wv.x);
            FMA2(acc[1][2 * k],     xa.y, wv.x);
            FMA2(acc[2][2 * k],     xc.x, wv.x);
            FMA2(acc[3][2 * k],     xc.y, wv.x);
            FMA2(acc[0][2 * k + 1], xa.x, wv.y);
            FMA2(acc[1][2 * k + 1], xa.y, wv.y);
            FMA2(acc[2][2 * k + 1], xc.x, wv.y);
            FMA2(acc[3][2 * k + 1], xc.y, wv.y);
        }
    }

    // Epilogue: bias, relu for evident, route to scratch / out
    #pragma unroll
    for (int o = 0; o < NOUT; o++) {
        float bias = (o < 13) ? pos_b[o] : (o == 13) ? reg_b[0] : off_b[o - 14];
        float4 vA, vB;
        vA.x = __uint_as_float((unsigned)(acc[0][o]))       + bias;
        vA.y = __uint_as_float((unsigned)(acc[0][o] >> 32)) + bias;
        vA.z = __uint_as_float((unsigned)(acc[1][o]))       + bias;
        vA.w = __uint_as_float((unsigned)(acc[1][o] >> 32)) + bias;
        vB.x = __uint_as_float((unsigned)(acc[2][o]))       + bias;
        vB.y = __uint_as_float((unsigned)(acc[2][o] >> 32)) + bias;
        vB.z = __uint_as_float((unsigned)(acc[3][o]))       + bias;
        vB.w = __uint_as_float((unsigned)(acc[3][o] >> 32)) + bias;
        if (o < 13) {
            vA.x = fmaxf(vA.x, 0.f); vA.y = fmaxf(vA.y, 0.f);
            vA.z = fmaxf(vA.z, 0.f); vA.w = fmaxf(vA.w, 0.f);
            vB.x = fmaxf(vB.x, 0.f); vB.y = fmaxf(vB.y, 0.f);
            vB.z = fmaxf(vB.z, 0.f); vB.w = fmaxf(vB.w, 0.f);
            float* dst = g_ev + (size_t)(b * 13 + o) * HW;
            *reinterpret_cast<float4*>(dst + pA) = vA;
            *reinterpret_cast<float4*>(dst + pB) = vB;
        } else if (o == 13) {
            float* dst = out + 2 * HW + (size_t)b * HW;   // x_reg block
            *reinterpret_cast<float4*>(dst + pA) = vA;
            *reinterpret_cast<float4*>(dst + pB) = vB;
        } else {
            float* dst = out + 4 * HW + (size_t)(b * 2 + (o - 14)) * HW; // x_off block
            *reinterpret_cast<float4*>(dst + pA) = vA;
            *reinterpret_cast<float4*>(dst + pB) = vB;
        }
    }
}

// ---------------- Kernel B: Hough vote conv + sigmoid ----------------
// 32x32 output tile per block; per channel load a 64x64 halo tile, gather the
// channel's region taps (offset list, uint4-vectorized), scale by 1/n_r.
__global__ void __launch_bounds__(1024) k_hough(float* __restrict__ out)
{
    __shared__ float tile[6144];    // [0,4096) data, [4096,6144) zero slab
    __shared__ uint4 soff[148];     // 1184 u16 offsets

    const int tid = threadIdx.x;
    if (tid < 148) soff[tid] = reinterpret_cast<const uint4*>(g_tab.off)[tid];
    for (int i = 4096 + tid; i < 6144; i += 1024) tile[i] = 0.f;

    const int b  = blockIdx.z;
    const int y0 = blockIdx.y * 32;
    const int x0 = blockIdx.x * 32;
    const int ty = tid >> 5, tx = tid & 31;
    const int base = ty * 64 + tx;

    float score = 0.f;
    for (int r = 0; r < 13; r++) {
        __syncthreads();   // zero slab / soff ready (r=0), prior reads done (r>0)
        const float* ev = g_ev + (size_t)(b * 13 + r) * HW;
        #pragma unroll
        for (int i = 0; i < 4; i++) {
            int idx = tid + i * 1024;
            int row = idx >> 6, col = idx & 63;
            int gy = y0 + row - 16, gx = x0 + col - 16;
            float v = 0.f;
            if ((unsigned)gy < (unsigned)H_IMG && (unsigned)gx < (unsigned)W_IMG)
                v = ev[gy * W_IMG + gx];
            tile[idx] = v;
        }
        __syncthreads();

        float sum = 0.f;
        const int j1 = g_tab.start[r + 1] >> 3;
        for (int j = g_tab.start[r] >> 3; j < j1; j++) {
            uint4 v = soff[j];
            sum += tile[base + (v.x & 0xFFFF)];
            sum += tile[base + (v.x >> 16)];
            sum += tile[base + (v.y & 0xFFFF)];
            sum += tile[base + (v.y >> 16)];
            sum += tile[base + (v.z & 0xFFFF)];
            sum += tile[base + (v.z >> 16)];
            sum += tile[base + (v.w & 0xFFFF)];
            sum += tile[base + (v.w >> 16)];
        }
        score += g_tab.w[r] * sum;
    }

    const int gy = y0 + ty, gx = x0 + tx;
    out[(size_t)b * HW + gy * W_IMG + gx] = 1.f / (1.f + expf(-score));
}

// ---------------- launch ----------------
extern "C" void kernel_launch(void* const* d_in, const int* in_sizes, int n_in,
                              void* d_out, int out_size)
{
    const float* x     = (const float*)d_in[0];
    const float* pos_w = (const float*)d_in[1];
    const float* pos_b = (const float*)d_in[2];
    const float* reg_w = (const float*)d_in[3];
    const float* reg_b = (const float*)d_in[4];
    const float* off_w = (const float*)d_in[5];
    const float* off_b = (const float*)d_in[6];
    float* out = (float*)d_out;

    dim3 gA(128, NB);
    k_head<<<gA, 128>>>(x, pos_w, pos_b, reg_w, reg_b, off_w, off_b, out);

    dim3 gB(W_IMG / 32, H_IMG / 32, NB);
    k_hough<<<gB, 1024>>>(out);
}

// round 3
// speedup vs baseline: 1.2879x; 1.2879x over previous
#include <cuda_runtime.h>
#include <math.h>

#define HW      131072      // 256*512
#define W_IMG   512
#define H_IMG   256
#define NC      256
#define NB      2
#define NOUT    16          // 13 pos + 1 reg + 2 off

// Scratch for evident = relu(pos conv): [2,13,H,W]
__device__ float g_ev[NB * 13 * HW];

// ---------------- compile-time Hough region geometry ----------------
// score(y,x) = sum_{iy,ix in [0,33)} w[region(16-iy,16-ix)] * e_{region(16-iy,16-ix)}(y+iy-16, x+ix-16)
// Angle bin via exact integer sign logic (matches numpy degrees(arctan2) which
// lands exactly on 0/90/180/270 for axis pixels). Validated correct in R1.
__host__ __device__ constexpr int region_of(int ys, int xs) {
    int r2 = ys * ys + xs * xs;
    if (r2 <= 4) return 0;
    int ring = (r2 <= 64) ? 0 : (r2 <= 256) ? 1 : 2;
    int bin = 0;
    if (ys > 0)      bin = (xs > 0) ? 0 : 1;
    else if (ys < 0) bin = (xs < 0) ? 2 : 3;
    else             bin = (xs > 0) ? 0 : 2;   // ys==0 row (origin is r2<=4)
    return 1 + ring * 4 + bin;
}

// Maximal horizontal runs of each region inside the 33x33 window.
struct SegTab {
    short iy[512];   // window row of run
    short a[512];    // first ix of run
    short b[512];    // last ix of run
    int   start[14]; // per-region [start, start+count)
    float w[13];     // 1 / region pixel count
};

__host__ __device__ constexpr SegTab make_segs() {
    SegTab t{};
    int cnt[13] = {};
    for (int iy = 0; iy < 33; iy++)
        for (int ix = 0; ix < 33; ix++)
            cnt[region_of(16 - iy, 16 - ix)]++;
    int pos = 0;
    for (int r = 0; r < 13; r++) {
        t.start[r] = pos;
        t.w[r] = 1.0f / (float)cnt[r];
        for (int iy = 0; iy < 33; iy++) {
            int ix = 0;
            while (ix < 33) {
                if (region_of(16 - iy, 16 - ix) == r) {
                    int a0 = ix;
                    while (ix < 33 && region_of(16 - iy, 16 - ix) == r) ix++;
                    t.iy[pos] = (short)iy;
                    t.a[pos]  = (short)a0;
                    t.b[pos]  = (short)(ix - 1);
                    pos++;
                } else ix++;
            }
        }
    }
    t.start[13] = pos;
    return t;
}

// ---------------- Kernel A: fused 1x1 convs (16 out channels) ----------------
// 8 pixels/thread, f32x2 packed FMA, weights in shared as duplicated {w,w} pairs.
// Software-pipelined: next c-pair's x loads prefetched into registers during the
// current pair's FMA block (covers DRAM latency at low occupancy).
#define FMA2(d, a, b) asm("fma.rn.f32x2 %0, %1, %2, %0;" : "+l"(d) : "l"(a), "l"(b))

__global__ void __launch_bounds__(128) k_head(
    const float* __restrict__ x,
    const float* __restrict__ pos_w, const float* __restrict__ pos_b,
    const float* __restrict__ reg_w, const float* __restrict__ reg_b,
    const float* __restrict__ off_w, const float* __restrict__ off_b,
    float* __restrict__ out)
{
    __shared__ __align__(16) unsigned long long wdup[NC * NOUT];

    const int tid = threadIdx.x;
    for (int i = tid; i < NC * NOUT; i += 128) {
        int c = i >> 4, o = i & 15;
        float w = (o < 13) ? pos_w[o * NC + c]
                : (o == 13) ? reg_w[c]
                : off_w[(o - 14) * NC + c];
        unsigned int u = __float_as_uint(w);
        wdup[i] = (unsigned long long)u | ((unsigned long long)u << 32);
    }
    __syncthreads();

    const int b  = blockIdx.y;
    const int pA = blockIdx.x * 1024 + tid * 4;   // 512 px group A
    const float* xpA = x + (size_t)b * NC * HW + pA;
    const float* xpB = xpA + 512;                  // 512 px group B

    unsigned long long acc[4][NOUT];
    #pragma unroll
    for (int g = 0; g < 4; g++)
        #pragma unroll
        for (int o = 0; o < NOUT; o++) acc[g][o] = 0ull;

    // pipeline registers: current pair (c, c+1), next pair (c+2, c+3)
    ulonglong2 a0 = *reinterpret_cast<const ulonglong2*>(xpA);
    ulonglong2 g0 = *reinterpret_cast<const ulonglong2*>(xpB);
    ulonglong2 a1 = *reinterpret_cast<const ulonglong2*>(xpA + HW);
    ulonglong2 g1 = *reinterpret_cast<const ulonglong2*>(xpB + HW);

    #define COMPUTE_C(cc, xa, xc)                                              \
    {                                                                          \
        const ulonglong2* wp = reinterpret_cast<const ulonglong2*>(wdup + (cc) * NOUT); \
        _Pragma("unroll")                                                      \
        for (int k = 0; k < 8; k++) {                                          \
            ulonglong2 wv = wp[k];                                             \
            FMA2(acc[0][2 * k],     (xa).x, wv.x);                             \
            FMA2(acc[1][2 * k],     (xa).y, wv.x);                             \
            FMA2(acc[2][2 * k],     (xc).x, wv.x);                             \
            FMA2(acc[3][2 * k],     (xc).y, wv.x);                             \
            FMA2(acc[0][2 * k + 1], (xa).x, wv.y);                             \
            FMA2(acc[1][2 * k + 1], (xa).y, wv.y);                             \
            FMA2(acc[2][2 * k + 1], (xc).x, wv.y);                             \
            FMA2(acc[3][2 * k + 1], (xc).y, wv.y);                             \
        }                                                                      \
    }

    #pragma unroll 1
    for (int c = 0; c < NC - 2; c += 2) {
        const float* p = xpA + (size_t)(c + 2) * HW;
        ulonglong2 na0 = *reinterpret_cast<const ulonglong2*>(p);
        ulonglong2 ng0 = *reinterpret_cast<const ulonglong2*>(p + 512);
        ulonglong2 na1 = *reinterpret_cast<const ulonglong2*>(p + HW);
        ulonglong2 ng1 = *reinterpret_cast<const ulonglong2*>(p + 512 + HW);
        COMPUTE_C(c,     a0, g0);
        COMPUTE_C(c + 1, a1, g1);
        a0 = na0; g0 = ng0; a1 = na1; g1 = ng1;
    }
    COMPUTE_C(NC - 2, a0, g0);
    COMPUTE_C(NC - 1, a1, g1);

    // Epilogue: bias, relu for evident, route to scratch / out
    #pragma unroll
    for (int o = 0; o < NOUT; o++) {
        float bias = (o < 13) ? pos_b[o] : (o == 13) ? reg_b[0] : off_b[o - 14];
        float4 vA, vB;
        vA.x = __uint_as_float((unsigned)(acc[0][o]))       + bias;
        vA.y = __uint_as_float((unsigned)(acc[0][o] >> 32)) + bias;
        vA.z = __uint_as_float((unsigned)(acc[1][o]))       + bias;
        vA.w = __uint_as_float((unsigned)(acc[1][o] >> 32)) + bias;
        vB.x = __uint_as_float((unsigned)(acc[2][o]))       + bias;
        vB.y = __uint_as_float((unsigned)(acc[2][o] >> 32)) + bias;
        vB.z = __uint_as_float((unsigned)(acc[3][o]))       + bias;
        vB.w = __uint_as_float((unsigned)(acc[3][o] >> 32)) + bias;
        if (o < 13) {
            vA.x = fmaxf(vA.x, 0.f); vA.y = fmaxf(vA.y, 0.f);
            vA.z = fmaxf(vA.z, 0.f); vA.w = fmaxf(vA.w, 0.f);
            vB.x = fmaxf(vB.x, 0.f); vB.y = fmaxf(vB.y, 0.f);
            vB.z = fmaxf(vB.z, 0.f); vB.w = fmaxf(vB.w, 0.f);
            float* dst = g_ev + (size_t)(b * 13 + o) * HW;
            *reinterpret_cast<float4*>(dst + pA)       = vA;
            *reinterpret_cast<float4*>(dst + pA + 512) = vB;
        } else if (o == 13) {
            float* dst = out + 2 * HW + (size_t)b * HW;   // x_reg block
            *reinterpret_cast<float4*>(dst + pA)       = vA;
            *reinterpret_cast<float4*>(dst + pA + 512) = vB;
        } else {
            float* dst = out + 4 * HW + (size_t)(b * 2 + (o - 14)) * HW; // x_off block
            *reinterpret_cast<float4*>(dst + pA)       = vA;
            *reinterpret_cast<float4*>(dst + pA + 512) = vB;
        }
    }
}

// ---------------- Kernel B: Hough vote conv + sigmoid ----------------
// 32x32 output tile per block. Per channel: build per-row prefix sums of the
// 64x64 halo tile in shared (warp scan, double-buffered, 1 sync/channel), then
// each region run = 2 LDS with COMPILE-TIME immediate offsets + subtract.
#define PSTR 65

// Fully-unrolled gather for region R: all offsets and the weight fold to
// immediates (loop bounds are constexpr ints; table is local constexpr).
template<int R>
__device__ __forceinline__ float gather_region(const float* __restrict__ buf, int pbase) {
    constexpr SegTab t = make_segs();
    constexpr int j0 = t.start[R];
    constexpr int j1 = t.start[R + 1];
    float s0 = 0.f, s1 = 0.f, s2 = 0.f, s3 = 0.f;
    #pragma unroll
    for (int j = j0; j < j1; j++) {
        int ro = t.iy[j] * PSTR;
        float d = buf[pbase + ro + t.b[j] + 1] - buf[pbase + ro + t.a[j]];
        int lane4 = j & 3;
        if      (lane4 == 0) s0 += d;
        else if (lane4 == 1) s1 += d;
        else if (lane4 == 2) s2 += d;
        else                 s3 += d;
    }
    return ((s0 + s1) + (s2 + s3)) * t.w[R];
}

template<int R> struct ChanLoop {
    static __device__ __forceinline__ float run(
        int b, int y0, int x0, int lane, int wrp, int pbase,
        float* __restrict__ sP0, float* __restrict__ sP1)
    {
        float* buf = (R & 1) ? sP1 : sP0;
        const float* ev = g_ev + (size_t)(b * 13 + R) * HW;

        // build prefix rows 2*wrp and 2*wrp+1 (each warp scans 2 rows of 64)
        #pragma unroll
        for (int k = 0; k < 2; k++) {
            int row = 2 * wrp + k;
            int gy  = y0 + row - 16;
            int gx  = x0 + 2 * lane - 16;
            float v0 = 0.f, v1 = 0.f;
            if ((unsigned)gy < (unsigned)H_IMG) {
                const float* rp = ev + gy * W_IMG;
                if ((unsigned)gx       < (unsigned)W_IMG) v0 = rp[gx];
                if ((unsigned)(gx + 1) < (unsigned)W_IMG) v1 = rp[gx + 1];
            }
            float s = v0 + v1;
            float inc = s;
            #pragma unroll
            for (int d = 1; d < 32; d <<= 1) {
                float n = __shfl_up_sync(0xffffffffu, inc, d);
                if (lane >= d) inc += n;
            }
            float excl = inc - s;
            float* rowp = buf + row * PSTR;   // rowp[j] = sum of cols [0, j)
            if (lane == 0) rowp[0] = 0.f;
            rowp[2 * lane + 1] = excl + v0;
            rowp[2 * lane + 2] = inc;
        }
        __syncthreads();
        // Double-buffer: next channel writes the OTHER buffer, and its sync
        // happens only after every warp finished this channel's reads.
        float part = gather_region<R>(buf, pbase);
        return part + ChanLoop<R + 1>::run(b, y0, x0, lane, wrp, pbase, sP0, sP1);
    }
};

template<> struct ChanLoop<13> {
    static __device__ __forceinline__ float run(int, int, int, int, int, int, float*, float*) {
        return 0.f;
    }
};

__global__ void __launch_bounds__(1024) k_hough(float* __restrict__ out)
{
    __shared__ float sP[2][64 * PSTR];

    const int tid  = threadIdx.x;
    const int lane = tid & 31;
    const int wrp  = tid >> 5;
    const int b  = blockIdx.z;
    const int y0 = blockIdx.y * 32;
    const int x0 = blockIdx.x * 32;
    const int pbase = wrp * PSTR + lane;   // output pixel (ty=wrp, tx=lane)

    float score = ChanLoop<0>::run(b, y0, x0, lane, wrp, pbase, sP[0], sP[1]);

    out[(size_t)b * HW + (y0 + wrp) * W_IMG + (x0 + lane)] = 1.f / (1.f + expf(-score));
}

// ---------------- launch ----------------
extern "C" void kernel_launch(void* const* d_in, const int* in_sizes, int n_in,
                              void* d_out, int out_size)
{
    const float* x     = (const float*)d_in[0];
    const float* pos_w = (const float*)d_in[1];
    const float* pos_b = (const float*)d_in[2];
    const float* reg_w = (const float*)d_in[3];
    const float* reg_b = (const float*)d_in[4];
    const float* off_w = (const float*)d_in[5];
    const float* off_b = (const float*)d_in[6];
    float* out = (float*)d_out;

    dim3 gA(128, NB);
    k_head<<<gA, 128>>>(x, pos_w, pos_b, reg_w, reg_b, off_w, off_b, out);

    dim3 gB(W_IMG / 32, H_IMG / 32, NB);
    k_hough<<<gB, 1024>>>(out);
}

// round 5
// speedup vs baseline: 1.4661x; 1.1384x over previous
#include <cuda_runtime.h>
#include <math.h>

#define HW      131072      // 256*512
#define W_IMG   512
#define H_IMG   256
#define NC      256
#define NB      2
#define NOUT    16          // 13 pos + 1 reg + 2 off

// Scratch for evident = relu(pos conv): [2,13,H,W]
__device__ float g_ev[NB * 13 * HW];

// ---------------- compile-time Hough region geometry ----------------
__host__ __device__ constexpr int region_of(int ys, int xs) {
    int r2 = ys * ys + xs * xs;
    if (r2 <= 4) return 0;
    int ring = (r2 <= 64) ? 0 : (r2 <= 256) ? 1 : 2;
    int bin = 0;
    if (ys > 0)      bin = (xs > 0) ? 0 : 1;
    else if (ys < 0) bin = (xs < 0) ? 2 : 3;
    else             bin = (xs > 0) ? 0 : 2;   // ys==0 row (origin is r2<=4)
    return 1 + ring * 4 + bin;
}

// Maximal horizontal runs of each region inside the 33x33 window.
struct SegTab {
    short iy[512];
    short a[512];
    short b[512];
    int   start[14];
    float w[13];
};

__host__ __device__ constexpr SegTab make_segs() {
    SegTab t{};
    int cnt[13] = {};
    for (int iy = 0; iy < 33; iy++)
        for (int ix = 0; ix < 33; ix++)
            cnt[region_of(16 - iy, 16 - ix)]++;
    int pos = 0;
    for (int r = 0; r < 13; r++) {
        t.start[r] = pos;
        t.w[r] = 1.0f / (float)cnt[r];
        for (int iy = 0; iy < 33; iy++) {
            int ix = 0;
            while (ix < 33) {
                if (region_of(16 - iy, 16 - ix) == r) {
                    int a0 = ix;
                    while (ix < 33 && region_of(16 - iy, 16 - ix) == r) ix++;
                    t.iy[pos] = (short)iy;
                    t.a[pos]  = (short)a0;
                    t.b[pos]  = (short)(ix - 1);
                    pos++;
                } else ix++;
            }
        }
    }
    t.start[13] = pos;
    return t;
}

// ---------------- Kernel A: fused 1x1 convs (16 out channels) ----------------
// 4 px/thread, f32x2 packed FMA. Inner loop batches 16 independent LDG.128
// (front-batched MLP=16) so per-SM in-flight bytes reach the ~22KB Little's-law
// requirement for full HBM bandwidth. 512 blocks -> ~3.5 warps/SMSP.
#define FMA2(d, a, b) asm("fma.rn.f32x2 %0, %1, %2, %0;" : "+l"(d) : "l"(a), "l"(b))
#define CBATCH 16

__global__ void __launch_bounds__(128, 3) k_head(
    const float* __restrict__ x,
    const float* __restrict__ pos_w, const float* __restrict__ pos_b,
    const float* __restrict__ reg_w, const float* __restrict__ reg_b,
    const float* __restrict__ off_w, const float* __restrict__ off_b,
    float* __restrict__ out)
{
    __shared__ __align__(16) unsigned long long wdup[NC * NOUT];

    const int tid = threadIdx.x;
    for (int i = tid; i < NC * NOUT; i += 128) {
        int c = i >> 4, o = i & 15;
        float w = (o < 13) ? pos_w[o * NC + c]
                : (o == 13) ? reg_w[c]
                : off_w[(o - 14) * NC + c];
        unsigned int u = __float_as_uint(w);
        wdup[i] = (unsigned long long)u | ((unsigned long long)u << 32);
    }
    __syncthreads();

    const int b  = blockIdx.y;
    const int p0 = blockIdx.x * 512 + tid * 4;   // 4 consecutive px
    const float* xp = x + (size_t)b * NC * HW + p0;

    unsigned long long acc[2][NOUT];
    #pragma unroll
    for (int g = 0; g < 2; g++)
        #pragma unroll
        for (int o = 0; o < NOUT; o++) acc[g][o] = 0ull;

    #pragma unroll 1
    for (int cb = 0; cb < NC; cb += CBATCH) {
        // front-batched independent loads (MLP = CBATCH)
        ulonglong2 xv[CBATCH];
        #pragma unroll
        for (int j = 0; j < CBATCH; j++)
            xv[j] = *reinterpret_cast<const ulonglong2*>(xp + (size_t)(cb + j) * HW);

        #pragma unroll
        for (int j = 0; j < CBATCH; j++) {
            const ulonglong2* wp =
                reinterpret_cast<const ulonglong2*>(wdup + (cb + j) * NOUT);
            #pragma unroll
            for (int k = 0; k < 8; k++) {
                ulonglong2 wv = wp[k];   // {w(2k),w(2k)}, {w(2k+1),w(2k+1)}
                FMA2(acc[0][2 * k],     xv[j].x, wv.x);
                FMA2(acc[1][2 * k],     xv[j].y, wv.x);
                FMA2(acc[0][2 * k + 1], xv[j].x, wv.y);
                FMA2(acc[1][2 * k + 1], xv[j].y, wv.y);
            }
        }
    }

    // Epilogue: bias, relu for evident, route to scratch / out
    #pragma unroll
    for (int o = 0; o < NOUT; o++) {
        float bias = (o < 13) ? pos_b[o] : (o == 13) ? reg_b[0] : off_b[o - 14];
        float4 v;
        v.x = __uint_as_float((unsigned)(acc[0][o]))       + bias;
        v.y = __uint_as_float((unsigned)(acc[0][o] >> 32)) + bias;
        v.z = __uint_as_float((unsigned)(acc[1][o]))       + bias;
        v.w = __uint_as_float((unsigned)(acc[1][o] >> 32)) + bias;
        if (o < 13) {
            v.x = fmaxf(v.x, 0.f); v.y = fmaxf(v.y, 0.f);
            v.z = fmaxf(v.z, 0.f); v.w = fmaxf(v.w, 0.f);
            float* dst = g_ev + (size_t)(b * 13 + o) * HW;
            *reinterpret_cast<float4*>(dst + p0) = v;
        } else if (o == 13) {
            float* dst = out + 2 * HW + (size_t)b * HW;   // x_reg block
            *reinterpret_cast<float4*>(dst + p0) = v;
        } else {
            float* dst = out + 4 * HW + (size_t)(b * 2 + (o - 14)) * HW; // x_off
            *reinterpret_cast<float4*>(dst + p0) = v;
        }
    }
}

// ---------------- Kernel B: Hough vote conv + sigmoid ----------------
#define PSTR 65

template<int R>
__device__ __forceinline__ float gather_region(const float* __restrict__ buf, int pbase) {
    constexpr SegTab t = make_segs();
    constexpr int j0 = t.start[R];
    constexpr int j1 = t.start[R + 1];
    float s0 = 0.f, s1 = 0.f, s2 = 0.f, s3 = 0.f;
    #pragma unroll
    for (int j = j0; j < j1; j++) {
        int ro = t.iy[j] * PSTR;
        float d = buf[pbase + ro + t.b[j] + 1] - buf[pbase + ro + t.a[j]];
        int lane4 = j & 3;
        if      (lane4 == 0) s0 += d;
        else if (lane4 == 1) s1 += d;
        else if (lane4 == 2) s2 += d;
        else                 s3 += d;
    }
    return ((s0 + s1) + (s2 + s3)) * t.w[R];
}

template<int R> struct ChanLoop {
    static __device__ __forceinline__ float run(
        int b, int y0, int x0, int lane, int wrp, int pbase,
        float* __restrict__ sP0, float* __restrict__ sP1)
    {
        float* buf = (R & 1) ? sP1 : sP0;
        const float* ev = g_ev + (size_t)(b * 13 + R) * HW;

        #pragma unroll
        for (int k = 0; k < 2; k++) {
            int row = 2 * wrp + k;
            int gy  = y0 + row - 16;
            int gx  = x0 + 2 * lane - 16;
            float v0 = 0.f, v1 = 0.f;
            if ((unsigned)gy < (unsigned)H_IMG) {
                const float* rp = ev + gy * W_IMG;
                if ((unsigned)gx       < (unsigned)W_IMG) v0 = rp[gx];
                if ((unsigned)(gx + 1) < (unsigned)W_IMG) v1 = rp[gx + 1];
            }
            float s = v0 + v1;
            float inc = s;
            #pragma unroll
            for (int d = 1; d < 32; d <<= 1) {
                float n = __shfl_up_sync(0xffffffffu, inc, d);
                if (lane >= d) inc += n;
            }
            float excl = inc - s;
            float* rowp = buf + row * PSTR;   // rowp[j] = sum of cols [0, j)
            if (lane == 0) rowp[0] = 0.f;
            rowp[2 * lane + 1] = excl + v0;
            rowp[2 * lane + 2] = inc;
        }
        __syncthreads();
        float part = gather_region<R>(buf, pbase);
        return part + ChanLoop<R + 1>::run(b, y0, x0, lane, wrp, pbase, sP0, sP1);
    }
};

template<> struct ChanLoop<13> {
    static __device__ __forceinline__ float run(int, int, int, int, int, int, float*, float*) {
        return 0.f;
    }
};

__global__ void __launch_bounds__(1024) k_hough(float* __restrict__ out)
{
    __shared__ float sP[2][64 * PSTR];

    const int tid  = threadIdx.x;
    const int lane = tid & 31;
    const int wrp  = tid >> 5;
    const int b  = blockIdx.z;
    const int y0 = blockIdx.y * 32;
    const int x0 = blockIdx.x * 32;
    const int pbase = wrp * PSTR + lane;

    float score = ChanLoop<0>::run(b, y0, x0, lane, wrp, pbase, sP[0], sP[1]);

    out[(size_t)b * HW + (y0 + wrp) * W_IMG + (x0 + lane)] = 1.f / (1.f + expf(-score));
}

// ---------------- launch ----------------
extern "C" void kernel_launch(void* const* d_in, const int* in_sizes, int n_in,
                              void* d_out, int out_size)
{
    const float* x     = (const float*)d_in[0];
    const float* pos_w = (const float*)d_in[1];
    const float* pos_b = (const float*)d_in[2];
    const float* reg_w = (const float*)d_in[3];
    const float* reg_b = (const float*)d_in[4];
    const float* off_w = (const float*)d_in[5];
    const float* off_b = (const float*)d_in[6];
    float* out = (float*)d_out;

    dim3 gA(HW / 512, NB);           // 256 x 2 = 512 blocks, 512 px each
    k_head<<<gA, 128>>>(x, pos_w, pos_b, reg_w, reg_b, off_w, off_b, out);

    dim3 gB(W_IMG / 32, H_IMG / 32, NB);
    k_hough<<<gB, 1024>>>(out);
}